// round 8
// baseline (speedup 1.0000x reference)
#include <cuda_runtime.h>
#include <cstdint>

#define PPTS   32
#define C_OUT  64
#define BN_EPS 1e-3f

#define NBLK1   740              // 148 SM * 5 resident blocks (single wave)
#define THREADS1 256
#define WARPS1   8

__device__ float g_partial[NBLK1 * 2 * C_OUT];
__device__ float g_scale[C_OUT];
__device__ float g_shift[C_OUT];

// ---- packed f32x2 helpers (Blackwell sm_100+) ------------------------------
typedef unsigned long long ull;
__device__ __forceinline__ ull pk2(float lo, float hi) {
    ull r; asm("mov.b64 %0, {%1, %2};" : "=l"(r) : "f"(lo), "f"(hi)); return r;
}
__device__ __forceinline__ ull fma2(ull a, ull b, ull c) {
    ull d; asm("fma.rn.f32x2 %0, %1, %2, %3;" : "=l"(d) : "l"(a), "l"(b), "l"(c)); return d;
}
__device__ __forceinline__ ull mul2(ull a, ull b) {
    ull d; asm("mul.rn.f32x2 %0, %1, %2;" : "=l"(d) : "l"(a), "l"(b)); return d;
}
__device__ __forceinline__ ull add2(ull a, ull b) {
    ull d; asm("add.rn.f32x2 %0, %1, %2;" : "=l"(d) : "l"(a), "l"(b)); return d;
}
__device__ __forceinline__ void unpk2(ull x, float& lo, float& hi) {
    unsigned a, b; asm("mov.b64 {%0, %1}, %2;" : "=r"(a), "=r"(b) : "l"(x));
    lo = __uint_as_float(a); hi = __uint_as_float(b);
}
__device__ __forceinline__ float lo2(ull x) { float l, h; unpk2(x, l, h); return l; }
__device__ __forceinline__ float hi2(ull x) { float l, h; unpk2(x, l, h); return h; }

// ---------------------------------------------------------------------------
// Pass 1 (R4 structure): warp = pillar; SoA smem tile; f32x2 packs point pairs.
// Counted unroll-4 quad loop (no jump table). Pre-affine max -> d_out direct.
// ---------------------------------------------------------------------------
__global__ __launch_bounds__(THREADS1, 5) void pfn_pass1(
    const float4* __restrict__ voxels,    // [N,32] float4
    const int*    __restrict__ npts_arr,  // [N]
    const float2* __restrict__ centers,   // [N]
    const float*  __restrict__ W,         // [64,9]
    float*        __restrict__ outmax,    // [N,64] pre-affine max (== d_out)
    int N)
{
    const int tid  = threadIdx.x;
    const int lane = tid & 31;
    const int wrp  = tid >> 5;
    const int oA = lane, oB = lane + 32;

    // lane-indexed epilogue weight table (keeps regs <= 48)
    __shared__ ull ew[5][32];
    if (tid < 32) {
        const float* wa_ = W + tid * 9;
        const float* wb_ = W + (tid + 32) * 9;
        ew[0][tid] = pk2(wa_[4], wb_[4]);
        ew[1][tid] = pk2(wa_[5], wb_[5]);
        ew[2][tid] = pk2(wa_[6], wb_[6]);
        ew[3][tid] = pk2(wa_[7], wb_[7]);
        ew[4][tid] = pk2(wa_[8], wb_[8]);
    }

    // quad-loop weights in registers (read by every fma2)
    const float* wa = W + oA * 9;
    const float* wb = W + oB * 9;
    const ull A0 = pk2(wa[0] + wa[4] + wa[7], wa[0] + wa[4] + wa[7]);
    const ull A1 = pk2(wa[1] + wa[5] + wa[8], wa[1] + wa[5] + wa[8]);
    const ull A2 = pk2(wa[2] + wa[6],         wa[2] + wa[6]);
    const ull A3 = pk2(wa[3],                 wa[3]);
    const ull B0 = pk2(wb[0] + wb[4] + wb[7], wb[0] + wb[4] + wb[7]);
    const ull B1 = pk2(wb[1] + wb[5] + wb[8], wb[1] + wb[5] + wb[8]);
    const ull B2 = pk2(wb[2] + wb[6],         wb[2] + wb[6]);
    const ull B3 = pk2(wb[3],                 wb[3]);

    __shared__ float vox_soa[WARPS1][4][PPTS];   // x[32] y[32] z[32] w[32]
    __syncthreads();                              // ew table visible

    ull sp  = 0ull;   // packed (sumA, sumB), bias folded
    ull s2p = 0ull;   // packed (sumsqA, sumsqB)

    const int stride = gridDim.x * WARPS1;
    int n = blockIdx.x * WARPS1 + wrp;

    float4 v = make_float4(0.f, 0.f, 0.f, 0.f);
    int np = 1;
    float2 c = make_float2(0.f, 0.f);
    if (n < N) {
        v  = voxels[(size_t)n * PPTS + lane];
        np = npts_arr[n];
        c  = centers[n];
    }

    while (n < N) {
        // SoA staging (4 conflict-free STS.32)
        vox_soa[wrp][0][lane] = v.x;
        vox_soa[wrp][1][lane] = v.y;
        vox_soa[wrp][2][lane] = v.z;
        vox_soa[wrp][3][lane] = v.w;
        __syncwarp();

        // mean reduction: (x,y) packed, z scalar (reference sums all 32 rows)
        ull  sxy = pk2(v.x, v.y);
        float sz = v.z;
        #pragma unroll
        for (int off = 16; off > 0; off >>= 1) {
            sxy = add2(sxy, __shfl_xor_sync(0xffffffffu, sxy, off));
            sz += __shfl_xor_sync(0xffffffffu, sz, off);
        }

        // distance-1 prefetch of next pillar
        const int n2 = n + stride;
        float4 v2 = v; int np2 = np; float2 c2 = c;
        if (n2 < N) {
            v2  = voxels[(size_t)n2 * PPTS + lane];
            np2 = npts_arr[n2];
            c2  = centers[n2];
        }

        // ---- quad loop: 4 points / iter (counted, unroll 4) ---------------
        float mA0 = -3.402823466e38f, mA1 = mA0, mB0 = mA0, mB1 = mA0;
        ull sA = 0ull, sB = 0ull, qA = 0ull, qB = 0ull;

        const char* base = (const char*)&vox_soa[wrp][0][0];
        const int nq = np >> 2;
        #pragma unroll 4
        for (int q = 0; q < nq; q++) {
            const ulonglong2 xq = *(const ulonglong2*)(base + q * 16);
            const ulonglong2 yq = *(const ulonglong2*)(base + 128 + q * 16);
            const ulonglong2 zq = *(const ulonglong2*)(base + 256 + q * 16);
            const ulonglong2 wq = *(const ulonglong2*)(base + 384 + q * 16);

            const ull yA01 = fma2(A0, xq.x, fma2(A1, yq.x, fma2(A2, zq.x, mul2(A3, wq.x))));
            const ull yA23 = fma2(A0, xq.y, fma2(A1, yq.y, fma2(A2, zq.y, mul2(A3, wq.y))));
            const ull yB01 = fma2(B0, xq.x, fma2(B1, yq.x, fma2(B2, zq.x, mul2(B3, wq.x))));
            const ull yB23 = fma2(B0, xq.y, fma2(B1, yq.y, fma2(B2, zq.y, mul2(B3, wq.y))));

            mA0 = fmaxf(mA0, fmaxf(lo2(yA01), lo2(yA23)));
            mA1 = fmaxf(mA1, fmaxf(hi2(yA01), hi2(yA23)));
            mB0 = fmaxf(mB0, fmaxf(lo2(yB01), lo2(yB23)));
            mB1 = fmaxf(mB1, fmaxf(hi2(yB01), hi2(yB23)));

            sA = add2(sA, add2(yA01, yA23));
            sB = add2(sB, add2(yB01, yB23));
            qA = fma2(yA01, yA01, fma2(yA23, yA23, qA));
            qB = fma2(yB01, yB01, fma2(yB23, yB23, qB));
        }
        float mA = fmaxf(mA0, mA1);
        float mB = fmaxf(mB0, mB1);

        // ---- scalar remainder (np & 3), weights aliased from packed regs --
        float sAr = 0.f, sBr = 0.f, qAr = 0.f, qBr = 0.f;
        for (int p = nq << 2; p < np; p++) {
            const float xx = vox_soa[wrp][0][p];
            const float yy = vox_soa[wrp][1][p];
            const float zz = vox_soa[wrp][2][p];
            const float ww = vox_soa[wrp][3][p];
            const float yA = fmaf(lo2(A0), xx, fmaf(lo2(A1), yy, fmaf(lo2(A2), zz, lo2(A3) * ww)));
            const float yB = fmaf(lo2(B0), xx, fmaf(lo2(B1), yy, fmaf(lo2(B2), zz, lo2(B3) * ww)));
            mA = fmaxf(mA, yA);
            mB = fmaxf(mB, yB);
            sAr += yA; sBr += yB;
            qAr = fmaf(yA, yA, qAr);
            qBr = fmaf(yB, yB, qBr);
        }

        // ---- epilogue: packed bias from smem table, fold into stats -------
        float sx, sy;
        unpk2(sxy, sx, sy);
        const float rnp = 1.0f / (float)np;
        const ull M0 = pk2(sx * rnp, sx * rnp);
        const ull M1 = pk2(sy * rnp, sy * rnp);
        const ull M2 = pk2(sz * rnp, sz * rnp);
        const ull CX = pk2(c.x, c.x);
        const ull CY = pk2(c.y, c.y);
        const ull bacc = fma2(ew[0][lane], M0,
                         fma2(ew[1][lane], M1,
                         fma2(ew[2][lane], M2,
                         fma2(ew[3][lane], CX, mul2(ew[4][lane], CY)))));
        const float bA = -lo2(bacc);
        const float bB = -hi2(bacc);

        float fA = mA + bA, fB = mB + bB;
        if (np < PPTS) {                 // padded points contribute exactly 0
            fA = fmaxf(fA, 0.0f);
            fB = fmaxf(fB, 0.0f);
        }
        outmax[(size_t)n * C_OUT + oA] = fA;
        outmax[(size_t)n * C_OUT + oB] = fB;

        const float SyA = lo2(sA) + hi2(sA) + sAr;
        const float QyA = lo2(qA) + hi2(qA) + qAr;
        const float SyB = lo2(sB) + hi2(sB) + sBr;
        const float QyB = lo2(qB) + hi2(qB) + qBr;

        const float npf = (float)np;
        const ull Sy2  = pk2(SyA, SyB);
        const ull Qy2  = pk2(QyA, QyB);
        const ull bp   = pk2(bA, bB);
        const ull npf2 = pk2(npf, npf);
        sp  = add2(sp, fma2(npf2, bp, Sy2));                            // Σ(y+b)
        s2p = add2(s2p, fma2(bp, fma2(npf2, bp, add2(Sy2, Sy2)), Qy2)); // Σ(y+b)²

        __syncwarp();
        v = v2; np = np2; c = c2; n = n2;
    }

    // deterministic block reduction across warps
    __shared__ float rsm[WARPS1][C_OUT];
    __shared__ float rqm[WARPS1][C_OUT];
    rsm[wrp][oA] = lo2(sp);  rsm[wrp][oB] = hi2(sp);
    rqm[wrp][oA] = lo2(s2p); rqm[wrp][oB] = hi2(s2p);
    __syncthreads();
    if (tid < C_OUT) {
        float ts = 0.0f, tq = 0.0f;
        #pragma unroll
        for (int g = 0; g < WARPS1; g++) { ts += rsm[g][tid]; tq += rqm[g][tid]; }
        g_partial[blockIdx.x * 2 * C_OUT + tid]         = ts;
        g_partial[blockIdx.x * 2 * C_OUT + C_OUT + tid] = tq;
    }
}

// ---------------------------------------------------------------------------
// Pass 2: parallel deterministic reduction -> BN scale/shift
// ---------------------------------------------------------------------------
#define P2_CHUNKS 16
__global__ __launch_bounds__(P2_CHUNKS * C_OUT) void pfn_pass2(
    const float* __restrict__ gamma, const float* __restrict__ beta, int N)
{
    const int tid = threadIdx.x;
    const int o = tid & (C_OUT - 1);
    const int chunk = tid >> 6;

    float s = 0.0f, q = 0.0f;
    for (int b = chunk; b < NBLK1; b += P2_CHUNKS) {
        s += g_partial[b * 2 * C_OUT + o];
        q += g_partial[b * 2 * C_OUT + C_OUT + o];
    }
    __shared__ float ss[P2_CHUNKS][C_OUT];
    __shared__ float qq[P2_CHUNKS][C_OUT];
    ss[chunk][o] = s;
    qq[chunk][o] = q;
    __syncthreads();
    if (tid < C_OUT) {
        float ts = 0.0f, tq = 0.0f;
        #pragma unroll
        for (int k = 0; k < P2_CHUNKS; k++) { ts += ss[k][tid]; tq += qq[k][tid]; }
        const float inv  = 1.0f / ((float)N * (float)PPTS);
        const float mean = ts * inv;
        const float var  = fmaf(-mean, mean, tq * inv);
        const float sc   = gamma[tid] * rsqrtf(var + BN_EPS);
        g_scale[tid] = sc;
        g_shift[tid] = fmaf(-sc, mean, beta[tid]);
    }
}

// ---------------------------------------------------------------------------
// Pass 3: in-place out = relu(scale * out + shift)  (scale > 0 since gamma==1,
// so the affine+relu commutes with the max computed in pass 1)
// ---------------------------------------------------------------------------
__global__ __launch_bounds__(256) void pfn_pass3(float* __restrict__ out, int N)
{
    __shared__ float sc_s[C_OUT], sh_s[C_OUT];
    if (threadIdx.x < C_OUT) {
        sc_s[threadIdx.x] = g_scale[threadIdx.x];
        sh_s[threadIdx.x] = g_shift[threadIdx.x];
    }
    __syncthreads();
    const int total4 = N * C_OUT / 4;
    for (int i = blockIdx.x * blockDim.x + threadIdx.x; i < total4;
         i += gridDim.x * blockDim.x) {
        float4 m = reinterpret_cast<const float4*>(out)[i];
        const int o = (i * 4) & (C_OUT - 1);
        m.x = fmaxf(fmaf(sc_s[o + 0], m.x, sh_s[o + 0]), 0.0f);
        m.y = fmaxf(fmaf(sc_s[o + 1], m.y, sh_s[o + 1]), 0.0f);
        m.z = fmaxf(fmaf(sc_s[o + 2], m.z, sh_s[o + 2]), 0.0f);
        m.w = fmaxf(fmaf(sc_s[o + 3], m.w, sh_s[o + 3]), 0.0f);
        reinterpret_cast<float4*>(out)[i] = m;
    }
}

// ---------------------------------------------------------------------------
extern "C" void kernel_launch(void* const* d_in, const int* in_sizes, int n_in,
                              void* d_out, int out_size)
{
    const float4* voxels  = (const float4*)d_in[0];
    const int*    npts    = (const int*)d_in[1];
    const float2* centers = (const float2*)d_in[2];
    const float*  W       = (const float*)d_in[3];
    const float*  gamma   = (const float*)d_in[4];
    const float*  beta    = (const float*)d_in[5];
    float*        out     = (float*)d_out;

    const int N = in_sizes[1];

    pfn_pass1<<<NBLK1, THREADS1>>>(voxels, npts, centers, W, out, N);
    pfn_pass2<<<1, P2_CHUNKS * C_OUT>>>(gamma, beta, N);
    pfn_pass3<<<1184, 256>>>(out, N);
}

// round 9
// speedup vs baseline: 1.1973x; 1.1973x over previous
#include <cuda_runtime.h>
#include <cstdint>

#define PPTS   32
#define C_OUT  64
#define BN_EPS 1e-3f

#define NBLK1   592              // 148 SM * 4 resident blocks
#define THREADS1 256
#define WARPS1   8

__device__ float g_partial[NBLK1 * 2 * C_OUT];
__device__ float g_scale[C_OUT];
__device__ float g_shift[C_OUT];

// ---- packed f32x2 helpers (Blackwell sm_100+) ------------------------------
typedef unsigned long long ull;
__device__ __forceinline__ ull pk2(float lo, float hi) {
    ull r; asm("mov.b64 %0, {%1, %2};" : "=l"(r) : "f"(lo), "f"(hi)); return r;
}
__device__ __forceinline__ ull fma2(ull a, ull b, ull c) {
    ull d; asm("fma.rn.f32x2 %0, %1, %2, %3;" : "=l"(d) : "l"(a), "l"(b), "l"(c)); return d;
}
__device__ __forceinline__ ull mul2(ull a, ull b) {
    ull d; asm("mul.rn.f32x2 %0, %1, %2;" : "=l"(d) : "l"(a), "l"(b)); return d;
}
__device__ __forceinline__ ull add2(ull a, ull b) {
    ull d; asm("add.rn.f32x2 %0, %1, %2;" : "=l"(d) : "l"(a), "l"(b)); return d;
}
__device__ __forceinline__ void unpk2(ull x, float& lo, float& hi) {
    unsigned a, b; asm("mov.b64 {%0, %1}, %2;" : "=r"(a), "=r"(b) : "l"(x));
    lo = __uint_as_float(a); hi = __uint_as_float(b);
}
__device__ __forceinline__ float lo2(ull x) { float l, h; unpk2(x, l, h); return l; }
__device__ __forceinline__ float hi2(ull x) { float l, h; unpk2(x, l, h); return h; }

// ---------------------------------------------------------------------------
// Pass 1 (R4 structure, verbatim): warp = pillar; SoA smem; f32x2 point pairs.
// Pre-affine per-(pillar,channel) max written directly into d_out.
// ---------------------------------------------------------------------------
__global__ __launch_bounds__(THREADS1, 4) void pfn_pass1(
    const float4* __restrict__ voxels,    // [N,32] float4
    const int*    __restrict__ npts_arr,  // [N]
    const float2* __restrict__ centers,   // [N]
    const float*  __restrict__ W,         // [64,9]
    float*        __restrict__ outmax,    // [N,64] pre-affine max (== d_out)
    int N)
{
    const int tid  = threadIdx.x;
    const int lane = tid & 31;
    const int wrp  = tid >> 5;
    const int oA = lane, oB = lane + 32;

    const float* wa = W + oA * 9;
    const float* wb = W + oB * 9;
    // folded weights, per channel (scalar)
    const float a0 = wa[0] + wa[4] + wa[7], b0 = wb[0] + wb[4] + wb[7];
    const float a1 = wa[1] + wa[5] + wa[8], b1 = wb[1] + wb[5] + wb[8];
    const float a2 = wa[2] + wa[6],         b2 = wb[2] + wb[6];
    const float a3 = wa[3],                 b3 = wb[3];
    // point-parity-packed duplicates for the quad loop
    const ull A0 = pk2(a0, a0), A1 = pk2(a1, a1), A2 = pk2(a2, a2), A3 = pk2(a3, a3);
    const ull B0 = pk2(b0, b0), B1 = pk2(b1, b1), B2 = pk2(b2, b2), B3 = pk2(b3, b3);
    const float w4a = wa[4], w5a = wa[5], w6a = wa[6], w7a = wa[7], w8a = wa[8];
    const float w4b = wb[4], w5b = wb[5], w6b = wb[6], w7b = wb[7], w8b = wb[8];

    // SoA: per warp, components contiguous: x[32] y[32] z[32] w[32]
    __shared__ float vox_soa[WARPS1][4][PPTS];

    ull sp  = 0ull;   // packed (sumA, sumB) with bias folded
    ull s2p = 0ull;   // packed (sumsqA, sumsqB)

    const int stride = gridDim.x * WARPS1;
    int n = blockIdx.x * WARPS1 + wrp;

    float4 v = make_float4(0.f, 0.f, 0.f, 0.f);
    int np = 1;
    float2 c = make_float2(0.f, 0.f);
    if (n < N) {
        v  = voxels[(size_t)n * PPTS + lane];
        np = npts_arr[n];
        c  = centers[n];
    }

    while (n < N) {
        // SoA staging: 4 conflict-free STS.32
        vox_soa[wrp][0][lane] = v.x;
        vox_soa[wrp][1][lane] = v.y;
        vox_soa[wrp][2][lane] = v.z;
        vox_soa[wrp][3][lane] = v.w;
        __syncwarp();

        // mean shuffles (reference sums ALL 32 rows, divides by np)
        ull  sxy = pk2(v.x, v.y);
        float sz = v.z;
        #pragma unroll
        for (int off = 16; off > 0; off >>= 1) {
            sxy = add2(sxy, __shfl_xor_sync(0xffffffffu, sxy, off));
            sz += __shfl_xor_sync(0xffffffffu, sz, off);
        }

        // prefetch next pillar
        const int n2 = n + stride;
        float4 v2 = v; int np2 = np; float2 c2 = c;
        if (n2 < N) {
            v2  = voxels[(size_t)n2 * PPTS + lane];
            np2 = npts_arr[n2];
            c2  = centers[n2];
        }

        // ---- quad loop: 4 points per iteration -------------------------
        float mA0 = -3.402823466e38f, mA1 = mA0, mB0 = mA0, mB1 = mA0;
        ull sA = 0ull, sB = 0ull, qA = 0ull, qB = 0ull;

        const char* base = (const char*)&vox_soa[wrp][0][0];
        const int nq = np >> 2;
        #pragma unroll 4
        for (int q = 0; q < nq; q++) {
            const ulonglong2 xq = *(const ulonglong2*)(base + q * 16);
            const ulonglong2 yq = *(const ulonglong2*)(base + 128 + q * 16);
            const ulonglong2 zq = *(const ulonglong2*)(base + 256 + q * 16);
            const ulonglong2 wq = *(const ulonglong2*)(base + 384 + q * 16);

            const ull yA01 = fma2(A0, xq.x, fma2(A1, yq.x, fma2(A2, zq.x, mul2(A3, wq.x))));
            const ull yA23 = fma2(A0, xq.y, fma2(A1, yq.y, fma2(A2, zq.y, mul2(A3, wq.y))));
            const ull yB01 = fma2(B0, xq.x, fma2(B1, yq.x, fma2(B2, zq.x, mul2(B3, wq.x))));
            const ull yB23 = fma2(B0, xq.y, fma2(B1, yq.y, fma2(B2, zq.y, mul2(B3, wq.y))));

            mA0 = fmaxf(mA0, fmaxf(lo2(yA01), lo2(yA23)));
            mA1 = fmaxf(mA1, fmaxf(hi2(yA01), hi2(yA23)));
            mB0 = fmaxf(mB0, fmaxf(lo2(yB01), lo2(yB23)));
            mB1 = fmaxf(mB1, fmaxf(hi2(yB01), hi2(yB23)));

            sA = add2(sA, add2(yA01, yA23));
            sB = add2(sB, add2(yB01, yB23));
            qA = fma2(yA01, yA01, fma2(yA23, yA23, qA));
            qB = fma2(yB01, yB01, fma2(yB23, yB23, qB));
        }
        float mA = fmaxf(mA0, mA1);
        float mB = fmaxf(mB0, mB1);

        // ---- scalar remainder (np & 3 points) ---------------------------
        float sAr = 0.f, sBr = 0.f, qAr = 0.f, qBr = 0.f;
        for (int p = nq << 2; p < np; p++) {
            const float xx = vox_soa[wrp][0][p];
            const float yy = vox_soa[wrp][1][p];
            const float zz = vox_soa[wrp][2][p];
            const float ww = vox_soa[wrp][3][p];
            const float yA = fmaf(a0, xx, fmaf(a1, yy, fmaf(a2, zz, a3 * ww)));
            const float yB = fmaf(b0, xx, fmaf(b1, yy, fmaf(b2, zz, b3 * ww)));
            mA = fmaxf(mA, yA);
            mB = fmaxf(mB, yB);
            sAr += yA; sBr += yB;
            qAr = fmaf(yA, yA, qAr);
            qBr = fmaf(yB, yB, qBr);
        }

        // ---- epilogue: fold bias into max / sum / sumsq -----------------
        float sx, sy;
        unpk2(sxy, sx, sy);
        const float rnp = 1.0f / (float)np;
        const float m0 = sx * rnp, m1 = sy * rnp, m2 = sz * rnp;
        const float bA = -(w4a * m0 + w5a * m1 + w6a * m2 + w7a * c.x + w8a * c.y);
        const float bB = -(w4b * m0 + w5b * m1 + w6b * m2 + w7b * c.x + w8b * c.y);

        float fA = mA + bA, fB = mB + bB;
        if (np < PPTS) {                 // padded points contribute exactly 0
            fA = fmaxf(fA, 0.0f);
            fB = fmaxf(fB, 0.0f);
        }
        outmax[(size_t)n * C_OUT + oA] = fA;
        outmax[(size_t)n * C_OUT + oB] = fB;

        const float SyA = lo2(sA) + hi2(sA) + sAr;
        const float QyA = lo2(qA) + hi2(qA) + qAr;
        const float SyB = lo2(sB) + hi2(sB) + sBr;
        const float QyB = lo2(qB) + hi2(qB) + qBr;

        const float npf = (float)np;
        const ull Sy2  = pk2(SyA, SyB);
        const ull Qy2  = pk2(QyA, QyB);
        const ull bp   = pk2(bA, bB);
        const ull npf2 = pk2(npf, npf);
        sp  = add2(sp, fma2(npf2, bp, Sy2));                            // Σ(y+b)
        s2p = add2(s2p, fma2(bp, fma2(npf2, bp, add2(Sy2, Sy2)), Qy2)); // Σ(y+b)²

        __syncwarp();
        v = v2; np = np2; c = c2; n = n2;
    }

    // deterministic block reduction across warps
    __shared__ float rsm[WARPS1][C_OUT];
    __shared__ float rqm[WARPS1][C_OUT];
    rsm[wrp][oA] = lo2(sp);  rsm[wrp][oB] = hi2(sp);
    rqm[wrp][oA] = lo2(s2p); rqm[wrp][oB] = hi2(s2p);
    __syncthreads();
    if (tid < C_OUT) {
        float ts = 0.0f, tq = 0.0f;
        #pragma unroll
        for (int g = 0; g < WARPS1; g++) { ts += rsm[g][tid]; tq += rqm[g][tid]; }
        g_partial[blockIdx.x * 2 * C_OUT + tid]         = ts;
        g_partial[blockIdx.x * 2 * C_OUT + C_OUT + tid] = tq;
    }
}

// ---------------------------------------------------------------------------
// Pass 2: parallel deterministic reduction -> BN scale/shift
// ---------------------------------------------------------------------------
#define P2_CHUNKS 16
__global__ __launch_bounds__(P2_CHUNKS * C_OUT) void pfn_pass2(
    const float* __restrict__ gamma, const float* __restrict__ beta, int N)
{
    const int tid = threadIdx.x;
    const int o = tid & (C_OUT - 1);
    const int chunk = tid >> 6;

    float s = 0.0f, q = 0.0f;
    for (int b = chunk; b < NBLK1; b += P2_CHUNKS) {
        s += g_partial[b * 2 * C_OUT + o];
        q += g_partial[b * 2 * C_OUT + C_OUT + o];
    }
    __shared__ float ss[P2_CHUNKS][C_OUT];
    __shared__ float qq[P2_CHUNKS][C_OUT];
    ss[chunk][o] = s;
    qq[chunk][o] = q;
    __syncthreads();
    if (tid < C_OUT) {
        float ts = 0.0f, tq = 0.0f;
        #pragma unroll
        for (int k = 0; k < P2_CHUNKS; k++) { ts += ss[k][tid]; tq += qq[k][tid]; }
        const float inv  = 1.0f / ((float)N * (float)PPTS);
        const float mean = ts * inv;
        const float var  = fmaf(-mean, mean, tq * inv);
        const float sc   = gamma[tid] * rsqrtf(var + BN_EPS);
        g_scale[tid] = sc;
        g_shift[tid] = fmaf(-sc, mean, beta[tid]);
    }
}

// ---------------------------------------------------------------------------
// Pass 3: in-place out = relu(scale * out + shift)  (scale > 0 since gamma==1,
// so affine+relu commutes with the max computed in pass 1)
// ---------------------------------------------------------------------------
__global__ __launch_bounds__(256) void pfn_pass3(float* __restrict__ out, int N)
{
    __shared__ float sc_s[C_OUT], sh_s[C_OUT];
    if (threadIdx.x < C_OUT) {
        sc_s[threadIdx.x] = g_scale[threadIdx.x];
        sh_s[threadIdx.x] = g_shift[threadIdx.x];
    }
    __syncthreads();
    const int total4 = N * C_OUT / 4;
    for (int i = blockIdx.x * blockDim.x + threadIdx.x; i < total4;
         i += gridDim.x * blockDim.x) {
        float4 m = reinterpret_cast<const float4*>(out)[i];
        const int o = (i * 4) & (C_OUT - 1);
        m.x = fmaxf(fmaf(sc_s[o + 0], m.x, sh_s[o + 0]), 0.0f);
        m.y = fmaxf(fmaf(sc_s[o + 1], m.y, sh_s[o + 1]), 0.0f);
        m.z = fmaxf(fmaf(sc_s[o + 2], m.z, sh_s[o + 2]), 0.0f);
        m.w = fmaxf(fmaf(sc_s[o + 3], m.w, sh_s[o + 3]), 0.0f);
        reinterpret_cast<float4*>(out)[i] = m;
    }
}

// ---------------------------------------------------------------------------
extern "C" void kernel_launch(void* const* d_in, const int* in_sizes, int n_in,
                              void* d_out, int out_size)
{
    const float4* voxels  = (const float4*)d_in[0];
    const int*    npts    = (const int*)d_in[1];
    const float2* centers = (const float2*)d_in[2];
    const float*  W       = (const float*)d_in[3];
    const float*  gamma   = (const float*)d_in[4];
    const float*  beta    = (const float*)d_in[5];
    float*        out     = (float*)d_out;

    const int N = in_sizes[1];

    pfn_pass1<<<NBLK1, THREADS1>>>(voxels, npts, centers, W, out, N);
    pfn_pass2<<<1, P2_CHUNKS * C_OUT>>>(gamma, beta, N);
    pfn_pass3<<<1184, 256>>>(out, N);
}